// round 1
// baseline (speedup 1.0000x reference)
#include <cuda_runtime.h>
#include <math.h>

#define BB   2
#define SS   2048
#define HIDD 2048
#define NH   16
#define HD   128
#define NKV  4
#define MR   (BB*SS)          // 4096 rows for projections
#define KVD  (NKV*HD)         // 512

// -------- scratch (device globals; no allocation allowed) --------
__device__ float g_tmpq[MR * HIDD];       // 33.5 MB
__device__ float g_tmpk[MR * KVD];        // 8.4 MB
__device__ float g_tmpv[MR * KVD];        // 8.4 MB
__device__ float g_q[BB * NH * SS * HD];  // 33.5 MB  [b,h,s,d]
__device__ float g_k[BB * NKV * SS * HD]; // 8.4 MB   [b,kv,s,d]
__device__ float g_v[BB * NKV * SS * HD]; // 8.4 MB   [b,kv,s,d]
__device__ float g_ctx[MR * HIDD];        // 33.5 MB  [b*s, h*d]

// ============================================================
// SGEMM: C[M,N] = A[M,K] @ W[K,N] + bias[N]
// BM=BN=128, BK=8, 256 threads, 8x8 micro-tile, float4 everywhere.
// M,K multiples of 8; N multiple of 128.
// ============================================================
__global__ __launch_bounds__(256) void sgemm_bias(
    const float* __restrict__ A, const float* __restrict__ W,
    const float* __restrict__ bias, float* __restrict__ C,
    int M, int N, int K)
{
    __shared__ float As[8][132];   // padded: conflict-free transposed stores
    __shared__ float Ws[8][128];

    const int tid = threadIdx.x;
    const int bm = blockIdx.y * 128;
    const int bn = blockIdx.x * 128;
    const int tr = tid >> 4;       // 0..15
    const int tc = tid & 15;       // 0..15

    // global load mapping
    const int arow = tid >> 1;           // 0..127
    const int ak   = (tid & 1) * 4;      // 0 or 4
    const int wk   = tid >> 5;           // 0..7
    const int wn   = (tid & 31) * 4;     // 0..124

    const float* Aptr = A + (size_t)(bm + arow) * K + ak;
    const float* Wptr = W + (size_t)wk * N + bn + wn;

    float acc[8][8];
    #pragma unroll
    for (int i = 0; i < 8; i++)
        #pragma unroll
        for (int j = 0; j < 8; j++) acc[i][j] = 0.f;

    for (int k0 = 0; k0 < K; k0 += 8) {
        float4 av = *(const float4*)(Aptr + k0);
        float4 wv = *(const float4*)(Wptr + (size_t)k0 * N);
        __syncthreads();
        As[ak + 0][arow] = av.x;
        As[ak + 1][arow] = av.y;
        As[ak + 2][arow] = av.z;
        As[ak + 3][arow] = av.w;
        *(float4*)&Ws[wk][wn] = wv;
        __syncthreads();

        #pragma unroll
        for (int k = 0; k < 8; k++) {
            float a[8], b[8];
            *(float4*)&a[0] = *(const float4*)&As[k][tr * 4];
            *(float4*)&a[4] = *(const float4*)&As[k][64 + tr * 4];
            *(float4*)&b[0] = *(const float4*)&Ws[k][tc * 4];
            *(float4*)&b[4] = *(const float4*)&Ws[k][64 + tc * 4];
            #pragma unroll
            for (int i = 0; i < 8; i++)
                #pragma unroll
                for (int j = 0; j < 8; j++)
                    acc[i][j] += a[i] * b[j];
        }
    }

    // epilogue: bias + store
    #pragma unroll
    for (int ih = 0; ih < 2; ih++) {
        #pragma unroll
        for (int ii = 0; ii < 4; ii++) {
            int row = bm + ih * 64 + tr * 4 + ii;
            #pragma unroll
            for (int jh = 0; jh < 2; jh++) {
                int col = bn + jh * 64 + tc * 4;
                float4 bsv = *(const float4*)(bias + col);
                float4 o;
                o.x = acc[ih * 4 + ii][jh * 4 + 0] + bsv.x;
                o.y = acc[ih * 4 + ii][jh * 4 + 1] + bsv.y;
                o.z = acc[ih * 4 + ii][jh * 4 + 2] + bsv.z;
                o.w = acc[ih * 4 + ii][jh * 4 + 3] + bsv.w;
                *(float4*)&C[(size_t)row * N + col] = o;
            }
        }
    }
}

// ============================================================
// RoPE + transpose: tmp[b*s, NHEADS*HD] -> out[b, head, s, d] with rope
// ============================================================
template <int NHEADS>
__global__ void rope_transpose(const float* __restrict__ tmp,
                               const float* __restrict__ cs,
                               const float* __restrict__ sn,
                               float* __restrict__ out)
{
    int idx = blockIdx.x * blockDim.x + threadIdx.x;  // over B*S*NHEADS*64
    const int TOT = BB * SS * NHEADS * (HD / 2);
    if (idx >= TOT) return;
    int p = idx & 63;
    int h = (idx >> 6) % NHEADS;
    int rest = idx / (64 * NHEADS);
    int s = rest % SS;
    int b = rest / SS;

    size_t irow = (size_t)(b * SS + s) * (NHEADS * HD) + h * HD + 2 * p;
    float xe = tmp[irow];
    float xo = tmp[irow + 1];
    float c = cs[s * 64 + p];
    float si = sn[s * 64 + p];
    float re = xe * c - xo * si;
    float im = xe * si + xo * c;
    size_t o = ((size_t)(b * NHEADS + h) * SS + s) * HD + 2 * p;
    out[o] = re;
    out[o + 1] = im;
}

__global__ void transpose_v(const float* __restrict__ tmp, float* __restrict__ out)
{
    int idx = blockIdx.x * blockDim.x + threadIdx.x;  // 2^21 total
    if (idx >= BB * SS * NKV * HD) return;
    int d = idx & 127;
    int h = (idx >> 7) & 3;
    int s = (idx >> 9) & 2047;
    int b = idx >> 20;
    out[((size_t)(b * NKV + h) * SS + s) * HD + d] =
        tmp[(size_t)(b * SS + s) * KVD + h * HD + d];
}

// ============================================================
// Flash-style causal attention. 64x64 tiles, D=128.
// Grid: (S/64, H, B). 256 threads.
// ============================================================
#define QT 64
#define KT 64
#define DP 132   // padded D row in smem
#define SP 68    // padded S-tile row

#define SMEM_FLOATS (3*QT*DP + QT*SP + 3*QT)
#define SMEM_BYTES  (SMEM_FLOATS*4)

__global__ __launch_bounds__(256, 1) void attn_kernel(
    const float* __restrict__ Qg, const float* __restrict__ Kg,
    const float* __restrict__ Vg, float* __restrict__ ctx)
{
    extern __shared__ float sm[];
    float* Qs   = sm;                  // 64*132
    float* Ks   = Qs + QT * DP;        // 64*132
    float* Vs   = Ks + KT * DP;        // 64*132
    float* Ssm  = Vs + KT * DP;        // 64*68
    float* m_sh = Ssm + QT * SP;       // 64
    float* l_sh = m_sh + QT;           // 64
    float* a_sh = l_sh + QT;           // 64

    const int tid = threadIdx.x;
    const int qb = blockIdx.x;         // 0..31
    const int h  = blockIdx.y;
    const int b  = blockIdx.z;
    const int kvh = h >> 2;            // REP = 4

    const float* Qbase = Qg + ((size_t)(b * NH + h) * SS + qb * QT) * HD;
    const float* Kbase = Kg + ((size_t)(b * NKV + kvh) * SS) * HD;
    const float* Vbase = Vg + ((size_t)(b * NKV + kvh) * SS) * HD;

    // load Q tile (64x128) via float4
    #pragma unroll
    for (int it = 0; it < 8; it++) {
        int lin = tid + it * 256;      // float4 slot 0..2047
        int row = lin >> 5;
        int d4  = (lin & 31) * 4;
        *(float4*)&Qs[row * DP + d4] = *(const float4*)(Qbase + row * HD + d4);
    }
    if (tid < QT) { m_sh[tid] = -1e30f; l_sh[tid] = 0.f; }

    // S-gemm lane mapping: warp grid 4x2 over 64x64; lanes 4x8
    const int warp  = tid >> 5;
    const int warpR = warp >> 1;       // 0..3  (16 q-rows each)
    const int warpC = warp & 1;        // 0..1  (32 k-cols each)
    const int lr = (tid & 31) >> 3;    // 0..3
    const int lc = tid & 7;            // 0..7
    const int qr0 = warpR * 16 + lr;   // q rows: qr0 + 4*i
    const int kc0 = warpC * 32 + lc;   // k cols: kc0 + 8*j

    // PV / output mapping: rows tr*4+i, cols tc + 16*j
    const int tr = tid >> 4;           // 0..15
    const int tc = tid & 15;           // 0..15

    float o[4][8];
    #pragma unroll
    for (int i = 0; i < 4; i++)
        #pragma unroll
        for (int j = 0; j < 8; j++) o[i][j] = 0.f;

    const float scale = 0.08838834764831845f;  // 1/sqrt(128)
    const int nkb = qb + 1;                    // causal: only kb <= qb

    for (int kb = 0; kb < nkb; kb++) {
        __syncthreads();  // previous iteration fully consumed smem
        // load K tile
        #pragma unroll
        for (int it = 0; it < 8; it++) {
            int lin = tid + it * 256;
            int row = lin >> 5;
            int d4  = (lin & 31) * 4;
            *(float4*)&Ks[row * DP + d4] =
                *(const float4*)(Kbase + (size_t)(kb * KT + row) * HD + d4);
        }
        __syncthreads();

        // S = Q @ K^T  (4x4 per thread, scattered layout, float4 k-steps)
        float acc[4][4];
        #pragma unroll
        for (int i = 0; i < 4; i++)
            #pragma unroll
            for (int j = 0; j < 4; j++) acc[i][j] = 0.f;

        #pragma unroll 8
        for (int d0 = 0; d0 < HD; d0 += 4) {
            float4 qf[4], kf[4];
            #pragma unroll
            for (int i = 0; i < 4; i++)
                qf[i] = *(const float4*)&Qs[(qr0 + 4 * i) * DP + d0];
            #pragma unroll
            for (int j = 0; j < 4; j++)
                kf[j] = *(const float4*)&Ks[(kc0 + 8 * j) * DP + d0];
            #pragma unroll
            for (int i = 0; i < 4; i++)
                #pragma unroll
                for (int j = 0; j < 4; j++)
                    acc[i][j] += qf[i].x * kf[j].x + qf[i].y * kf[j].y
                               + qf[i].z * kf[j].z + qf[i].w * kf[j].w;
        }
        // scale + causal mask + store to Ssm
        #pragma unroll
        for (int i = 0; i < 4; i++) {
            int qg = qb * QT + qr0 + 4 * i;
            #pragma unroll
            for (int j = 0; j < 4; j++) {
                int kg = kb * KT + kc0 + 8 * j;
                float v = acc[i][j] * scale;
                if (kg > qg) v = -1e30f;
                Ssm[(qr0 + 4 * i) * SP + kc0 + 8 * j] = v;
            }
        }
        __syncthreads();

        // load V tile (independent of softmax below)
        #pragma unroll
        for (int it = 0; it < 8; it++) {
            int lin = tid + it * 256;
            int row = lin >> 5;
            int d4  = (lin & 31) * 4;
            *(float4*)&Vs[row * DP + d4] =
                *(const float4*)(Vbase + (size_t)(kb * KT + row) * HD + d4);
        }

        // online softmax: 4 threads per row
        {
            int r  = tid >> 2;
            int c0 = (tid & 3) * 16;
            float mloc = -1e30f;
            #pragma unroll
            for (int c = 0; c < 16; c++) mloc = fmaxf(mloc, Ssm[r * SP + c0 + c]);
            mloc = fmaxf(mloc, __shfl_xor_sync(0xffffffffu, mloc, 1));
            mloc = fmaxf(mloc, __shfl_xor_sync(0xffffffffu, mloc, 2));
            float mold = m_sh[r];
            float mnew = fmaxf(mold, mloc);
            float sum = 0.f;
            #pragma unroll
            for (int c = 0; c < 16; c++) {
                float p = __expf(Ssm[r * SP + c0 + c] - mnew);
                Ssm[r * SP + c0 + c] = p;
                sum += p;
            }
            sum += __shfl_xor_sync(0xffffffffu, sum, 1);
            sum += __shfl_xor_sync(0xffffffffu, sum, 2);
            if ((tid & 3) == 0) {
                float alpha = __expf(mold - mnew);
                l_sh[r] = l_sh[r] * alpha + sum;
                m_sh[r] = mnew;
                a_sh[r] = alpha;
            }
        }
        __syncthreads();

        // O = O*alpha + P @ V
        float al[4];
        #pragma unroll
        for (int i = 0; i < 4; i++) al[i] = a_sh[tr * 4 + i];
        #pragma unroll
        for (int i = 0; i < 4; i++)
            #pragma unroll
            for (int j = 0; j < 8; j++) o[i][j] *= al[i];

        #pragma unroll 4
        for (int kk = 0; kk < KT; kk++) {
            float pv[4];
            #pragma unroll
            for (int i = 0; i < 4; i++) pv[i] = Ssm[(tr * 4 + i) * SP + kk];
            float vv[8];
            #pragma unroll
            for (int j = 0; j < 8; j++) vv[j] = Vs[kk * DP + tc + 16 * j];
            #pragma unroll
            for (int i = 0; i < 4; i++)
                #pragma unroll
                for (int j = 0; j < 8; j++)
                    o[i][j] += pv[i] * vv[j];
        }
    }
    __syncthreads();

    // normalize + write ctx[b*s, h*128 + col]
    #pragma unroll
    for (int i = 0; i < 4; i++) {
        int srow = qb * QT + tr * 4 + i;
        float inv = 1.f / l_sh[tr * 4 + i];
        size_t base = (size_t)(b * SS + srow) * HIDD + h * HD + tc;
        #pragma unroll
        for (int j = 0; j < 8; j++)
            ctx[base + 16 * j] = o[i][j] * inv;
    }
}

// ============================================================
// launch
// ============================================================
extern "C" void kernel_launch(void* const* d_in, const int* in_sizes, int n_in,
                              void* d_out, int out_size)
{
    const float* query = (const float*)d_in[0];
    const float* key   = (const float*)d_in[1];
    const float* value = (const float*)d_in[2];
    // d_in[3] = mask (unused: equivalent to causal -inf under fp32 softmax)
    const float* fcos  = (const float*)d_in[4];
    const float* fsin  = (const float*)d_in[5];
    const float* Wq = (const float*)d_in[6];
    const float* bq = (const float*)d_in[7];
    const float* Wk = (const float*)d_in[8];
    const float* bk = (const float*)d_in[9];
    const float* Wv = (const float*)d_in[10];
    const float* bv = (const float*)d_in[11];
    const float* Wo = (const float*)d_in[12];
    const float* bo = (const float*)d_in[13];
    float* out = (float*)d_out;

    float *tmpq, *tmpk, *tmpv, *qT, *kT, *vT, *ctx;
    cudaGetSymbolAddress((void**)&tmpq, g_tmpq);
    cudaGetSymbolAddress((void**)&tmpk, g_tmpk);
    cudaGetSymbolAddress((void**)&tmpv, g_tmpv);
    cudaGetSymbolAddress((void**)&qT,   g_q);
    cudaGetSymbolAddress((void**)&kT,   g_k);
    cudaGetSymbolAddress((void**)&vT,   g_v);
    cudaGetSymbolAddress((void**)&ctx,  g_ctx);

    cudaFuncSetAttribute(attn_kernel,
                         cudaFuncAttributeMaxDynamicSharedMemorySize, SMEM_BYTES);

    // projections
    sgemm_bias<<<dim3(HIDD / 128, MR / 128), 256>>>(query, Wq, bq, tmpq, MR, HIDD, HIDD);
    sgemm_bias<<<dim3(KVD  / 128, MR / 128), 256>>>(key,   Wk, bk, tmpk, MR, KVD,  HIDD);
    sgemm_bias<<<dim3(KVD  / 128, MR / 128), 256>>>(value, Wv, bv, tmpv, MR, KVD,  HIDD);

    // rope + layout transforms
    rope_transpose<NH><<<(BB * SS * NH * 64) / 256, 256>>>(tmpq, fcos, fsin, qT);
    rope_transpose<NKV><<<(BB * SS * NKV * 64) / 256, 256>>>(tmpk, fcos, fsin, kT);
    transpose_v<<<(BB * SS * NKV * HD) / 256, 256>>>(tmpv, vT);

    // attention
    attn_kernel<<<dim3(SS / QT, NH, BB), 256, SMEM_BYTES>>>(qT, kT, vT, ctx);

    // output projection
    sgemm_bias<<<dim3(HIDD / 128, MR / 128), 256>>>(ctx, Wo, bo, out, MR, HIDD, HIDD);
}